// round 16
// baseline (speedup 1.0000x reference)
#include <cuda_runtime.h>
#include <cuda_bf16.h>
#include <cstdint>

#define B_  32
#define C_  256
#define HW_ 64
#define AS_ 8
#define T_  64    // AS*AS
#define CT_ (C_ * T_)

typedef unsigned int u32;

// ---------------- scratch (device globals; batch-major [b][c][t]) ----------------
__device__ float g_PR[B_ * CT_];
__device__ float g_PD[B_ * CT_];
__device__ float g_Q [B_ * CT_];
__device__ float g_K [B_ * CT_];
__device__ float g_V [B_ * CT_];
__device__ float g_Apart[4 * B_ * T_ * T_];
__device__ float g_F [B_ * CT_];

// ---------------- tf32 helpers ----------------
__device__ __forceinline__ void tf32_split(float x, u32& hi, u32& lo) {
    u32 h;
    asm("cvt.rna.tf32.f32 %0, %1;" : "=r"(h) : "f"(x));
    float lf = x - __uint_as_float(h);
    u32 l;
    asm("cvt.rna.tf32.f32 %0, %1;" : "=r"(l) : "f"(lf));
    hi = h; lo = l;
}
__device__ __forceinline__ void mma_tf32(float* c, const u32* a, const u32* b) {
    asm volatile(
        "mma.sync.aligned.m16n8k8.row.col.f32.tf32.tf32.f32 "
        "{%0,%1,%2,%3}, {%4,%5,%6,%7}, {%8,%9}, {%0,%1,%2,%3};"
        : "+f"(c[0]), "+f"(c[1]), "+f"(c[2]), "+f"(c[3])
        : "r"(a[0]), "r"(a[1]), "r"(a[2]), "r"(a[3]), "r"(b[0]), "r"(b[1]));
}

// ---------------- 1) 8x8 avg pool (F_d first w/ evict-first, F_rgb last cached) -----------
__global__ void pool_kernel(const float* __restrict__ Frgb, const float* __restrict__ Fd) {
    int bid   = blockIdx.x;
    int which = bid >> 13;
    int plane = bid & 8191;
    const float* src = (which ? Frgb : Fd) + (size_t)plane * (HW_ * HW_);
    float* dst = (which ? g_PR : g_PD) + (size_t)plane * T_;

    __shared__ float part[128];
    int t = threadIdx.x;
    int chunk = t & 15;
    int i     = t >> 4;
    const float4* p = (const float4*)src;
    float s = 0.f;
#pragma unroll
    for (int r = 0; r < 8; r++) {
        float4 v = which ? p[(i * 8 + r) * 16 + chunk]
                         : __ldcs(&p[(i * 8 + r) * 16 + chunk]);
        s += (v.x + v.y) + (v.z + v.w);
    }
    part[t] = s;
    __syncthreads();
    if (t < 64) {
        int pi = t >> 3, pj = t & 7;
        dst[t] = (part[pi * 16 + 2 * pj] + part[pi * 16 + 2 * pj + 1]) * (1.0f / 64.0f);
    }
}

// ---------------- 2) QKV: 3xTF32 tensor-core GEMM (proven) ----------------
__global__ void __launch_bounds__(128) qkv_kernel(
        const float* __restrict__ Wq, const float* __restrict__ bq,
        const float* __restrict__ Wk, const float* __restrict__ bk,
        const float* __restrict__ Wv, const float* __restrict__ bv) {
    int b  = blockIdx.x;
    int o0 = blockIdx.y * 64;
    int z  = blockIdx.z;
    const float* W; const float* bias; const float* P; float* Out;
    if (z == 0)      { W = Wq; bias = bq; P = g_PR; Out = g_Q; }
    else if (z == 1) { W = Wk; bias = bk; P = g_PD; Out = g_K; }
    else             { W = Wv; bias = bv; P = g_PD; Out = g_V; }

    __shared__ float Whi[64][36], Wlo[64][36];
    __shared__ float Phi[32][72], Plo[32][72];

    int tid  = threadIdx.x;
    int warp = tid >> 5;
    int lane = tid & 31;
    int g    = lane >> 2;
    int tig  = lane & 3;
    int mw   = warp * 16;

    const float* Pb = P + ((size_t)b * CT_);

    float acc[8][4];
#pragma unroll
    for (int nt = 0; nt < 8; nt++)
#pragma unroll
        for (int j = 0; j < 4; j++) acc[nt][j] = 0.f;

    for (int kc = 0; kc < C_; kc += 32) {
#pragma unroll
        for (int q = 0; q < 4; q++) {
            int l = tid + q * 128;
            int row = l >> 3, c4 = l & 7;
            float4 v = *(const float4*)&W[(size_t)(o0 + row) * C_ + kc + c4 * 4];
            u32 h, lo;
            tf32_split(v.x, h, lo); Whi[row][c4*4+0] = __uint_as_float(h); Wlo[row][c4*4+0] = __uint_as_float(lo);
            tf32_split(v.y, h, lo); Whi[row][c4*4+1] = __uint_as_float(h); Wlo[row][c4*4+1] = __uint_as_float(lo);
            tf32_split(v.z, h, lo); Whi[row][c4*4+2] = __uint_as_float(h); Wlo[row][c4*4+2] = __uint_as_float(lo);
            tf32_split(v.w, h, lo); Whi[row][c4*4+3] = __uint_as_float(h); Wlo[row][c4*4+3] = __uint_as_float(lo);
        }
#pragma unroll
        for (int q = 0; q < 4; q++) {
            int l = tid + q * 128;
            int row = l >> 4, c4 = l & 15;
            float4 v = *(const float4*)&Pb[(size_t)(kc + row) * T_ + c4 * 4];
            u32 h, lo;
            tf32_split(v.x, h, lo); Phi[row][c4*4+0] = __uint_as_float(h); Plo[row][c4*4+0] = __uint_as_float(lo);
            tf32_split(v.y, h, lo); Phi[row][c4*4+1] = __uint_as_float(h); Plo[row][c4*4+1] = __uint_as_float(lo);
            tf32_split(v.z, h, lo); Phi[row][c4*4+2] = __uint_as_float(h); Plo[row][c4*4+2] = __uint_as_float(lo);
            tf32_split(v.w, h, lo); Phi[row][c4*4+3] = __uint_as_float(h); Plo[row][c4*4+3] = __uint_as_float(lo);
        }
        __syncthreads();
#pragma unroll
        for (int kk = 0; kk < 4; kk++) {
            int k0 = kk * 8;
            u32 ah[4], al[4];
            ah[0] = __float_as_uint(Whi[mw + g    ][k0 + tig    ]);
            ah[1] = __float_as_uint(Whi[mw + g + 8][k0 + tig    ]);
            ah[2] = __float_as_uint(Whi[mw + g    ][k0 + tig + 4]);
            ah[3] = __float_as_uint(Whi[mw + g + 8][k0 + tig + 4]);
            al[0] = __float_as_uint(Wlo[mw + g    ][k0 + tig    ]);
            al[1] = __float_as_uint(Wlo[mw + g + 8][k0 + tig    ]);
            al[2] = __float_as_uint(Wlo[mw + g    ][k0 + tig + 4]);
            al[3] = __float_as_uint(Wlo[mw + g + 8][k0 + tig + 4]);
#pragma unroll
            for (int nt = 0; nt < 8; nt++) {
                int n = nt * 8 + g;
                u32 bh[2], bl[2];
                bh[0] = __float_as_uint(Phi[k0 + tig    ][n]);
                bh[1] = __float_as_uint(Phi[k0 + tig + 4][n]);
                bl[0] = __float_as_uint(Plo[k0 + tig    ][n]);
                bl[1] = __float_as_uint(Plo[k0 + tig + 4][n]);
                mma_tf32(acc[nt], ah, bh);
                mma_tf32(acc[nt], ah, bl);
                mma_tf32(acc[nt], al, bh);
            }
        }
        __syncthreads();
    }

    float* Ob = Out + ((size_t)b * CT_);
    int mA = o0 + mw + g;
    int mB = mA + 8;
    float bA = bias[mA], bB = bias[mB];
#pragma unroll
    for (int nt = 0; nt < 8; nt++) {
        int col = nt * 8 + 2 * tig;
        *(float2*)&Ob[(size_t)mA * T_ + col] = make_float2(acc[nt][0] + bA, acc[nt][1] + bA);
        *(float2*)&Ob[(size_t)mB * T_ + col] = make_float2(acc[nt][2] + bB, acc[nt][3] + bB);
    }
}

// ---------------- 3) partial A (proven) ----------------
__global__ void attn_partial_kernel() {
    int b  = blockIdx.x;
    int c0 = blockIdx.y * 64;
    __shared__ float Qs[64][64];
    __shared__ float Ks[64][64];
    int tid = threadIdx.x;
    const float* Qb = g_Q + ((size_t)b * CT_) + (size_t)c0 * T_;
    const float* Kb = g_K + ((size_t)b * CT_) + (size_t)c0 * T_;
#pragma unroll
    for (int q = 0; q < 4; q++) {
        int l = tid + q * 256;
        int row = l >> 4, c4 = l & 15;
        *(float4*)&Qs[row][c4 * 4] = *(const float4*)&Qb[(size_t)row * T_ + c4 * 4];
        *(float4*)&Ks[row][c4 * 4] = *(const float4*)&Kb[(size_t)row * T_ + c4 * 4];
    }
    __syncthreads();
    int m0 = (tid >> 4) * 4;
    int n0 = (tid & 15) * 4;
    float acc[4][4] = {};
#pragma unroll
    for (int k = 0; k < 64; k++) {
        float4 av  = *(const float4*)&Qs[k][m0];
        float4 bv4 = *(const float4*)&Ks[k][n0];
        float aa[4] = {av.x, av.y, av.z, av.w};
        float bb[4] = {bv4.x, bv4.y, bv4.z, bv4.w};
#pragma unroll
        for (int i = 0; i < 4; i++)
#pragma unroll
            for (int j = 0; j < 4; j++)
                acc[i][j] = fmaf(aa[i], bb[j], acc[i][j]);
    }
    float* Ap = g_Apart + (((size_t)blockIdx.y * B_ + b) * (T_ * T_));
#pragma unroll
    for (int i = 0; i < 4; i++)
        *(float4*)&Ap[(m0 + i) * T_ + n0] =
            make_float4(acc[i][0], acc[i][1], acc[i][2], acc[i][3]);
}

// ---------------- 4) fused: reduce partials + softmax + Fatt slice (padded Vs) ------------
// grid (B, 8 chunks of 32 channels), 256 threads.
__global__ void softmax_fatt_kernel() {
    int b = blockIdx.x, cc = blockIdx.y;
    __shared__ float As[64][68];
    __shared__ float Vs[32][68];   // padded: kills the 4-way conflict R14 fixed in fatt
    int tid = threadIdx.x;

    // --- phase 1: As[t][s] = sum_p Apart[p][b][t][s] (L2-hot) ---
#pragma unroll
    for (int q = 0; q < 4; q++) {
        int l = tid + q * 256;
        int row = l >> 4, c4 = l & 15;
        size_t off = (size_t)b * (T_ * T_) + row * T_ + c4 * 4;
        float4 s = *(const float4*)&g_Apart[off];
#pragma unroll
        for (int p = 1; p < 4; p++) {
            float4 v = *(const float4*)&g_Apart[(size_t)p * B_ * (T_ * T_) + off];
            s.x += v.x; s.y += v.y; s.z += v.z; s.w += v.w;
        }
        *(float4*)&As[row][c4 * 4] = s;
    }
    const float* Vb = g_V + ((size_t)b * CT_) + (size_t)cc * 32 * T_;
#pragma unroll
    for (int q = 0; q < 2; q++) {
        int l = tid + q * 256;
        int row = l >> 4, c4 = l & 15;
        *(float4*)&Vs[row][c4 * 4] = *(const float4*)&Vb[(size_t)row * T_ + c4 * 4];
    }
    __syncthreads();

    // --- phase 2: row softmax (8 warps x 8 rows) ---
    {
        int warp = tid >> 5, lane = tid & 31;
#pragma unroll
        for (int rr = 0; rr < 8; rr++) {
            int r = warp * 8 + rr;
            float v0 = As[r][lane], v1 = As[r][lane + 32];
            float m = fmaxf(v0, v1);
#pragma unroll
            for (int off = 16; off; off >>= 1) m = fmaxf(m, __shfl_xor_sync(0xffffffffu, m, off));
            float e0 = __expf(v0 - m), e1 = __expf(v1 - m);
            float s = e0 + e1;
#pragma unroll
            for (int off = 16; off; off >>= 1) s += __shfl_xor_sync(0xffffffffu, s, off);
            float inv = 1.0f / s;
            As[r][lane]      = e0 * inv;
            As[r][lane + 32] = e1 * inv;
        }
    }
    __syncthreads();

    // --- phase 3: Fatt[c][t] = sum_s V[c][s] * A[t][s] ---
    int cl = tid >> 3;
    int t0 = tid & 7;
    float acc[8] = {};
#pragma unroll
    for (int s4 = 0; s4 < 16; s4++) {
        float4 v = *(const float4*)&Vs[cl][s4 * 4];
#pragma unroll
        for (int j = 0; j < 8; j++) {
            float4 a = *(const float4*)&As[t0 + 8 * j][s4 * 4];
            acc[j] = fmaf(v.x, a.x, acc[j]);
            acc[j] = fmaf(v.y, a.y, acc[j]);
            acc[j] = fmaf(v.z, a.z, acc[j]);
            acc[j] = fmaf(v.w, a.w, acc[j]);
        }
    }
    float* Fb = g_F + ((size_t)b * CT_) + (size_t)(cc * 32 + cl) * T_;
#pragma unroll
    for (int j = 0; j < 8; j++) Fb[t0 + 8 * j] = acc[j];
}

// ---------------- 5) upsample+blend: two-pass + evict-first stores (R14 WIN) ---------------
__global__ void upsample_blend_kernel(const float* __restrict__ Frgb,
                                      const float* __restrict__ alphap,
                                      float* __restrict__ out) {
    int plane = (B_ * C_ - 1) - blockIdx.x;
    __shared__ float Fs[64];
    __shared__ float uw[8][64];
    __shared__ int   i0s[64];
    __shared__ int   i1s[64];
    __shared__ float fs[64];
    int tid = threadIdx.x;
    if (tid < 64) {
        Fs[tid] = g_F[(size_t)plane * T_ + tid];
        float s  = (tid + 0.5f) * 0.125f - 0.5f;
        float fl = floorf(s);
        int   i0 = (int)fl;
        fs[tid]  = s - fl;
        i0s[tid] = i0 < 0 ? 0 : i0;
        i1s[tid] = (i0 + 1) > 7 ? 7 : (i0 + 1);
    }
    __syncthreads();
#pragma unroll
    for (int q = 0; q < 2; q++) {
        int l = tid + q * 256;
        int i = l >> 6, w = l & 63;
        float v0 = Fs[i * 8 + i0s[w]];
        float v1 = Fs[i * 8 + i1s[w]];
        uw[i][w] = v0 + fs[w] * (v1 - v0);
    }
    __syncthreads();

    float alpha = *alphap;
    float beta  = 1.0f - alpha;
    const float4* rp = (const float4*)(Frgb + (size_t)plane * (HW_ * HW_));
    float4*       op = (float4*)(out  + (size_t)plane * (HW_ * HW_));
#pragma unroll
    for (int q = 0; q < 4; q++) {
        int i4 = tid + q * 256;
        int h  = i4 >> 4;
        int w4 = i4 & 15;
        int   y0 = i0s[h], y1 = i1s[h]; float fy = fs[h];
        float4 t = *(const float4*)&uw[y0][w4 * 4];
        float4 bq4 = *(const float4*)&uw[y1][w4 * 4];
        float4 r = rp[i4];
        float4 o;
        o.x = alpha * (t.x + fy * (bq4.x - t.x)) + beta * r.x;
        o.y = alpha * (t.y + fy * (bq4.y - t.y)) + beta * r.y;
        o.z = alpha * (t.z + fy * (bq4.z - t.z)) + beta * r.z;
        o.w = alpha * (t.w + fy * (bq4.w - t.w)) + beta * r.w;
        __stcs(&op[i4], o);
    }
}

// ---------------- launch ----------------
extern "C" void kernel_launch(void* const* d_in, const int* in_sizes, int n_in,
                              void* d_out, int out_size) {
    const float* Frgb  = (const float*)d_in[0];
    const float* Fd    = (const float*)d_in[1];
    const float* Wq    = (const float*)d_in[2];
    const float* bq    = (const float*)d_in[3];
    const float* Wk    = (const float*)d_in[4];
    const float* bk    = (const float*)d_in[5];
    const float* Wv    = (const float*)d_in[6];
    const float* bv    = (const float*)d_in[7];
    const float* alpha = (const float*)d_in[8];
    float* out = (float*)d_out;

    pool_kernel<<<2 * B_ * C_, 128>>>(Frgb, Fd);
    qkv_kernel<<<dim3(B_, 4, 3), 128>>>(Wq, bq, Wk, bk, Wv, bv);
    attn_partial_kernel<<<dim3(B_, 4), 256>>>();
    softmax_fatt_kernel<<<dim3(B_, 8), 256>>>();
    upsample_blend_kernel<<<B_ * C_, 256>>>(Frgb, alpha, out);
}

// round 17
// speedup vs baseline: 1.0442x; 1.0442x over previous
#include <cuda_runtime.h>
#include <cuda_bf16.h>
#include <cstdint>

#define B_  32
#define C_  256
#define HW_ 64
#define AS_ 8
#define T_  64    // AS*AS
#define CT_ (C_ * T_)

typedef unsigned int u32;

// ---------------- scratch (device globals; batch-major [b][c][t]) ----------------
__device__ float g_PR[B_ * CT_];
__device__ float g_PD[B_ * CT_];
__device__ float g_Q [B_ * CT_];
__device__ float g_K [B_ * CT_];
__device__ float g_V [B_ * CT_];
__device__ float g_Apart[4 * B_ * T_ * T_];
__device__ float g_A [B_ * T_ * T_];
__device__ float g_F [B_ * CT_];

// ---------------- tf32 helpers ----------------
__device__ __forceinline__ void tf32_split(float x, u32& hi, u32& lo) {
    u32 h;
    asm("cvt.rna.tf32.f32 %0, %1;" : "=r"(h) : "f"(x));
    float lf = x - __uint_as_float(h);
    u32 l;
    asm("cvt.rna.tf32.f32 %0, %1;" : "=r"(l) : "f"(lf));
    hi = h; lo = l;
}
__device__ __forceinline__ void mma_tf32(float* c, const u32* a, const u32* b) {
    asm volatile(
        "mma.sync.aligned.m16n8k8.row.col.f32.tf32.tf32.f32 "
        "{%0,%1,%2,%3}, {%4,%5,%6,%7}, {%8,%9}, {%0,%1,%2,%3};"
        : "+f"(c[0]), "+f"(c[1]), "+f"(c[2]), "+f"(c[3])
        : "r"(a[0]), "r"(a[1]), "r"(a[2]), "r"(a[3]), "r"(b[0]), "r"(b[1]));
}

// ---------------- 1) 8x8 avg pool (F_d first w/ evict-first, F_rgb last cached) -----------
__global__ void pool_kernel(const float* __restrict__ Frgb, const float* __restrict__ Fd) {
    int bid   = blockIdx.x;
    int which = bid >> 13;
    int plane = bid & 8191;
    const float* src = (which ? Frgb : Fd) + (size_t)plane * (HW_ * HW_);
    float* dst = (which ? g_PR : g_PD) + (size_t)plane * T_;

    __shared__ float part[128];
    int t = threadIdx.x;
    int chunk = t & 15;
    int i     = t >> 4;
    const float4* p = (const float4*)src;
    float s = 0.f;
#pragma unroll
    for (int r = 0; r < 8; r++) {
        float4 v = which ? p[(i * 8 + r) * 16 + chunk]
                         : __ldcs(&p[(i * 8 + r) * 16 + chunk]);
        s += (v.x + v.y) + (v.z + v.w);
    }
    part[t] = s;
    __syncthreads();
    if (t < 64) {
        int pi = t >> 3, pj = t & 7;
        dst[t] = (part[pi * 16 + 2 * pj] + part[pi * 16 + 2 * pj + 1]) * (1.0f / 64.0f);
    }
}

// ---------------- 2) QKV: 3xTF32 tensor-core GEMM (PDL-gated) ----------------
__global__ void __launch_bounds__(128) qkv_kernel(
        const float* __restrict__ Wq, const float* __restrict__ bq,
        const float* __restrict__ Wk, const float* __restrict__ bk,
        const float* __restrict__ Wv, const float* __restrict__ bv) {
    cudaGridDependencySynchronize();   // wait for pool before reading g_PR/g_PD
    int b  = blockIdx.x;
    int o0 = blockIdx.y * 64;
    int z  = blockIdx.z;
    const float* W; const float* bias; const float* P; float* Out;
    if (z == 0)      { W = Wq; bias = bq; P = g_PR; Out = g_Q; }
    else if (z == 1) { W = Wk; bias = bk; P = g_PD; Out = g_K; }
    else             { W = Wv; bias = bv; P = g_PD; Out = g_V; }

    __shared__ float Whi[64][36], Wlo[64][36];
    __shared__ float Phi[32][72], Plo[32][72];

    int tid  = threadIdx.x;
    int warp = tid >> 5;
    int lane = tid & 31;
    int g    = lane >> 2;
    int tig  = lane & 3;
    int mw   = warp * 16;

    const float* Pb = P + ((size_t)b * CT_);

    float acc[8][4];
#pragma unroll
    for (int nt = 0; nt < 8; nt++)
#pragma unroll
        for (int j = 0; j < 4; j++) acc[nt][j] = 0.f;

    for (int kc = 0; kc < C_; kc += 32) {
#pragma unroll
        for (int q = 0; q < 4; q++) {
            int l = tid + q * 128;
            int row = l >> 3, c4 = l & 7;
            float4 v = *(const float4*)&W[(size_t)(o0 + row) * C_ + kc + c4 * 4];
            u32 h, lo;
            tf32_split(v.x, h, lo); Whi[row][c4*4+0] = __uint_as_float(h); Wlo[row][c4*4+0] = __uint_as_float(lo);
            tf32_split(v.y, h, lo); Whi[row][c4*4+1] = __uint_as_float(h); Wlo[row][c4*4+1] = __uint_as_float(lo);
            tf32_split(v.z, h, lo); Whi[row][c4*4+2] = __uint_as_float(h); Wlo[row][c4*4+2] = __uint_as_float(lo);
            tf32_split(v.w, h, lo); Whi[row][c4*4+3] = __uint_as_float(h); Wlo[row][c4*4+3] = __uint_as_float(lo);
        }
#pragma unroll
        for (int q = 0; q < 4; q++) {
            int l = tid + q * 128;
            int row = l >> 4, c4 = l & 15;
            float4 v = *(const float4*)&Pb[(size_t)(kc + row) * T_ + c4 * 4];
            u32 h, lo;
            tf32_split(v.x, h, lo); Phi[row][c4*4+0] = __uint_as_float(h); Plo[row][c4*4+0] = __uint_as_float(lo);
            tf32_split(v.y, h, lo); Phi[row][c4*4+1] = __uint_as_float(h); Plo[row][c4*4+1] = __uint_as_float(lo);
            tf32_split(v.z, h, lo); Phi[row][c4*4+2] = __uint_as_float(h); Plo[row][c4*4+2] = __uint_as_float(lo);
            tf32_split(v.w, h, lo); Phi[row][c4*4+3] = __uint_as_float(h); Plo[row][c4*4+3] = __uint_as_float(lo);
        }
        __syncthreads();
#pragma unroll
        for (int kk = 0; kk < 4; kk++) {
            int k0 = kk * 8;
            u32 ah[4], al[4];
            ah[0] = __float_as_uint(Whi[mw + g    ][k0 + tig    ]);
            ah[1] = __float_as_uint(Whi[mw + g + 8][k0 + tig    ]);
            ah[2] = __float_as_uint(Whi[mw + g    ][k0 + tig + 4]);
            ah[3] = __float_as_uint(Whi[mw + g + 8][k0 + tig + 4]);
            al[0] = __float_as_uint(Wlo[mw + g    ][k0 + tig    ]);
            al[1] = __float_as_uint(Wlo[mw + g + 8][k0 + tig    ]);
            al[2] = __float_as_uint(Wlo[mw + g    ][k0 + tig + 4]);
            al[3] = __float_as_uint(Wlo[mw + g + 8][k0 + tig + 4]);
#pragma unroll
            for (int nt = 0; nt < 8; nt++) {
                int n = nt * 8 + g;
                u32 bh[2], bl[2];
                bh[0] = __float_as_uint(Phi[k0 + tig    ][n]);
                bh[1] = __float_as_uint(Phi[k0 + tig + 4][n]);
                bl[0] = __float_as_uint(Plo[k0 + tig    ][n]);
                bl[1] = __float_as_uint(Plo[k0 + tig + 4][n]);
                mma_tf32(acc[nt], ah, bh);
                mma_tf32(acc[nt], ah, bl);
                mma_tf32(acc[nt], al, bh);
            }
        }
        __syncthreads();
    }

    float* Ob = Out + ((size_t)b * CT_);
    int mA = o0 + mw + g;
    int mB = mA + 8;
    float bA = bias[mA], bB = bias[mB];
#pragma unroll
    for (int nt = 0; nt < 8; nt++) {
        int col = nt * 8 + 2 * tig;
        *(float2*)&Ob[(size_t)mA * T_ + col] = make_float2(acc[nt][0] + bA, acc[nt][1] + bA);
        *(float2*)&Ob[(size_t)mB * T_ + col] = make_float2(acc[nt][2] + bB, acc[nt][3] + bB);
    }
}

// ---------------- 3) partial A (PDL-gated) ----------------
__global__ void attn_partial_kernel() {
    cudaGridDependencySynchronize();   // wait for qkv before reading g_Q/g_K
    int b  = blockIdx.x;
    int c0 = blockIdx.y * 64;
    __shared__ float Qs[64][64];
    __shared__ float Ks[64][64];
    int tid = threadIdx.x;
    const float* Qb = g_Q + ((size_t)b * CT_) + (size_t)c0 * T_;
    const float* Kb = g_K + ((size_t)b * CT_) + (size_t)c0 * T_;
#pragma unroll
    for (int q = 0; q < 4; q++) {
        int l = tid + q * 256;
        int row = l >> 4, c4 = l & 15;
        *(float4*)&Qs[row][c4 * 4] = *(const float4*)&Qb[(size_t)row * T_ + c4 * 4];
        *(float4*)&Ks[row][c4 * 4] = *(const float4*)&Kb[(size_t)row * T_ + c4 * 4];
    }
    __syncthreads();
    int m0 = (tid >> 4) * 4;
    int n0 = (tid & 15) * 4;
    float acc[4][4] = {};
#pragma unroll
    for (int k = 0; k < 64; k++) {
        float4 av  = *(const float4*)&Qs[k][m0];
        float4 bv4 = *(const float4*)&Ks[k][n0];
        float aa[4] = {av.x, av.y, av.z, av.w};
        float bb[4] = {bv4.x, bv4.y, bv4.z, bv4.w};
#pragma unroll
        for (int i = 0; i < 4; i++)
#pragma unroll
            for (int j = 0; j < 4; j++)
                acc[i][j] = fmaf(aa[i], bb[j], acc[i][j]);
    }
    float* Ap = g_Apart + (((size_t)blockIdx.y * B_ + b) * (T_ * T_));
#pragma unroll
    for (int i = 0; i < 4; i++)
        *(float4*)&Ap[(m0 + i) * T_ + n0] =
            make_float4(acc[i][0], acc[i][1], acc[i][2], acc[i][3]);
}

// ---------------- 4) reduce 4 partials + row softmax (PDL-gated) ----------------
__global__ void softmax_kernel() {
    cudaGridDependencySynchronize();   // wait for attn_partial before reading g_Apart
    int b  = blockIdx.x;
    int r0 = blockIdx.y * 16;
    int tid = threadIdx.x;
    int warp = tid >> 5, lane = tid & 31;
#pragma unroll
    for (int rr = 0; rr < 2; rr++) {
        int r = r0 + warp * 2 + rr;
        size_t base = (size_t)b * (T_ * T_) + r * T_;
        float v0 = 0.f, v1 = 0.f;
#pragma unroll
        for (int p = 0; p < 4; p++) {
            size_t pb = ((size_t)p * B_) * (T_ * T_) + base;
            v0 += g_Apart[pb + lane];
            v1 += g_Apart[pb + lane + 32];
        }
        float m = fmaxf(v0, v1);
#pragma unroll
        for (int off = 16; off; off >>= 1) m = fmaxf(m, __shfl_xor_sync(0xffffffffu, m, off));
        float e0 = __expf(v0 - m), e1 = __expf(v1 - m);
        float s = e0 + e1;
#pragma unroll
        for (int off = 16; off; off >>= 1) s += __shfl_xor_sync(0xffffffffu, s, off);
        float inv = 1.0f / s;
        g_A[base + lane]      = e0 * inv;
        g_A[base + lane + 32] = e1 * inv;
    }
}

// ---------------- 5) Fatt (padded Vs, PDL-gated) ----------------
__global__ void fatt_kernel() {
    cudaGridDependencySynchronize();   // wait for softmax before reading g_A
    int b = blockIdx.x, cc = blockIdx.y;
    __shared__ float As[64][68];
    __shared__ float Vs[32][68];
    int tid = threadIdx.x;
    const float* Ab = g_A + ((size_t)b * T_ * T_);
#pragma unroll
    for (int q = 0; q < 4; q++) {
        int l = tid + q * 256;
        int row = l >> 4, c4 = l & 15;
        *(float4*)&As[row][c4 * 4] = *(const float4*)&Ab[row * T_ + c4 * 4];
    }
    const float* Vb = g_V + ((size_t)b * CT_) + (size_t)cc * 32 * T_;
#pragma unroll
    for (int q = 0; q < 2; q++) {
        int l = tid + q * 256;
        int row = l >> 4, c4 = l & 15;
        *(float4*)&Vs[row][c4 * 4] = *(const float4*)&Vb[(size_t)row * T_ + c4 * 4];
    }
    __syncthreads();
    int cl = tid >> 3;
    int t0 = tid & 7;
    float acc[8] = {};
#pragma unroll
    for (int s4 = 0; s4 < 16; s4++) {
        float4 v = *(const float4*)&Vs[cl][s4 * 4];
#pragma unroll
        for (int j = 0; j < 8; j++) {
            float4 a = *(const float4*)&As[t0 + 8 * j][s4 * 4];
            acc[j] = fmaf(v.x, a.x, acc[j]);
            acc[j] = fmaf(v.y, a.y, acc[j]);
            acc[j] = fmaf(v.z, a.z, acc[j]);
            acc[j] = fmaf(v.w, a.w, acc[j]);
        }
    }
    float* Fb = g_F + ((size_t)b * CT_) + (size_t)(cc * 32 + cl) * T_;
#pragma unroll
    for (int j = 0; j < 8; j++) Fb[t0 + 8 * j] = acc[j];
}

// ---------------- 6) upsample+blend (two-pass, evict-first stores, PDL-gated) --------------
__global__ void upsample_blend_kernel(const float* __restrict__ Frgb,
                                      const float* __restrict__ alphap,
                                      float* __restrict__ out) {
    cudaGridDependencySynchronize();   // wait for fatt before reading g_F
    int plane = (B_ * C_ - 1) - blockIdx.x;
    __shared__ float Fs[64];
    __shared__ float uw[8][64];
    __shared__ int   i0s[64];
    __shared__ int   i1s[64];
    __shared__ float fs[64];
    int tid = threadIdx.x;
    if (tid < 64) {
        Fs[tid] = g_F[(size_t)plane * T_ + tid];
        float s  = (tid + 0.5f) * 0.125f - 0.5f;
        float fl = floorf(s);
        int   i0 = (int)fl;
        fs[tid]  = s - fl;
        i0s[tid] = i0 < 0 ? 0 : i0;
        i1s[tid] = (i0 + 1) > 7 ? 7 : (i0 + 1);
    }
    __syncthreads();
#pragma unroll
    for (int q = 0; q < 2; q++) {
        int l = tid + q * 256;
        int i = l >> 6, w = l & 63;
        float v0 = Fs[i * 8 + i0s[w]];
        float v1 = Fs[i * 8 + i1s[w]];
        uw[i][w] = v0 + fs[w] * (v1 - v0);
    }
    __syncthreads();

    float alpha = *alphap;
    float beta  = 1.0f - alpha;
    const float4* rp = (const float4*)(Frgb + (size_t)plane * (HW_ * HW_));
    float4*       op = (float4*)(out  + (size_t)plane * (HW_ * HW_));
#pragma unroll
    for (int q = 0; q < 4; q++) {
        int i4 = tid + q * 256;
        int h  = i4 >> 4;
        int w4 = i4 & 15;
        int   y0 = i0s[h], y1 = i1s[h]; float fy = fs[h];
        float4 t = *(const float4*)&uw[y0][w4 * 4];
        float4 bq4 = *(const float4*)&uw[y1][w4 * 4];
        float4 r = rp[i4];
        float4 o;
        o.x = alpha * (t.x + fy * (bq4.x - t.x)) + beta * r.x;
        o.y = alpha * (t.y + fy * (bq4.y - t.y)) + beta * r.y;
        o.z = alpha * (t.z + fy * (bq4.z - t.z)) + beta * r.z;
        o.w = alpha * (t.w + fy * (bq4.w - t.w)) + beta * r.w;
        __stcs(&op[i4], o);
    }
}

// ---------------- launch (PDL chaining: overlap launch latency with predecessor tail) ------
template <typename F, typename... Args>
static inline void launch_pdl(F func, dim3 grid, dim3 block, Args... args) {
    cudaLaunchConfig_t cfg = {};
    cfg.gridDim  = grid;
    cfg.blockDim = block;
    cudaLaunchAttribute attr[1];
    attr[0].id = cudaLaunchAttributeProgrammaticStreamSerialization;
    attr[0].val.programmaticStreamSerializationAllowed = 1;
    cfg.attrs = attr;
    cfg.numAttrs = 1;
    cudaLaunchKernelEx(&cfg, func, args...);
}

extern "C" void kernel_launch(void* const* d_in, const int* in_sizes, int n_in,
                              void* d_out, int out_size) {
    const float* Frgb  = (const float*)d_in[0];
    const float* Fd    = (const float*)d_in[1];
    const float* Wq    = (const float*)d_in[2];
    const float* bq    = (const float*)d_in[3];
    const float* Wk    = (const float*)d_in[4];
    const float* bk    = (const float*)d_in[5];
    const float* Wv    = (const float*)d_in[6];
    const float* bv    = (const float*)d_in[7];
    const float* alpha = (const float*)d_in[8];
    float* out = (float*)d_out;

    pool_kernel<<<2 * B_ * C_, 128>>>(Frgb, Fd);
    launch_pdl(qkv_kernel, dim3(B_, 4, 3), dim3(128), Wq, bq, Wk, bk, Wv, bv);
    launch_pdl(attn_partial_kernel, dim3(B_, 4), dim3(256));
    launch_pdl(softmax_kernel, dim3(B_, 4), dim3(256));
    launch_pdl(fatt_kernel, dim3(B_, 8), dim3(256));
    launch_pdl(upsample_blend_kernel, dim3(B_ * C_), dim3(256), Frgb, alpha, out);
}